// round 4
// baseline (speedup 1.0000x reference)
#include <cuda_runtime.h>

// ArnoldCat ^7, n=1024: out[a,b] <- in[(239a+169b)%1024, (338a+239b)%1024].
// Lattice tiling (round 3) + fully vectorized 128-bit global accesses (round 4).
//
// Basis: (a,b) = (169k', j'-239k'), source = (169j', k'+239j').
// Tile (m,n): k'=32m+k, j'=32n+j.
//  Read row j: source row 169j', pixels colbase..colbase+35 where colbase=(32m+239j')&~3
//    -> 27 aligned float4 (LDG.128). Useful pixel k sits at s_j + k, s_j=(3j)&3.
//  Write row k: output row 169kp, pixels shifted by delta_k=(-k)&3 so the 32-pixel
//    segment starts 16B-aligned -> 24 aligned float4 (STG.128). Needs tile rows
//    j in [delta, delta+32) -> load 35 rows (j=0..34).
// SMEM: 35 rows x 32 float4, XOR-fold swizzle (quad ^ ((j+(j>>3))&7)).

static constexpr unsigned ROW_F4  = 768u;            // float4 per image row
static constexpr unsigned IMG_F4  = 1024u * ROW_F4;  // float4 per image
static constexpr unsigned THREADS = 256u;
static constexpr unsigned BLOCKS  = 16u * 32u * 32u; // batch x m x n

__global__ void __launch_bounds__(THREADS)
arnold_vec_kernel(const float4* __restrict__ in4, float4* __restrict__ out4) {
    __shared__ float4 tile4[35 * 32];                // 17920 B

    const unsigned id    = blockIdx.x;
    const unsigned n     = id & 31u;
    const unsigned m     = (id >> 5) & 31u;
    const unsigned batch = id >> 10;
    const unsigned lane  = threadIdx.x & 31u;
    const unsigned warp  = threadIdx.x >> 5;

    const float4* inb  = in4  + batch * IMG_F4;
    float4*       outb = out4 + batch * IMG_F4;

    // ---- Phase 1: load 35 source row-segments, 27 aligned float4 each ----
    if (lane < 27u) {
        float4 v[5];
        unsigned slot[5];
        #pragma unroll
        for (unsigned it = 0; it < 4u; ++it) {
            unsigned j  = warp + 8u * it;                       // 0..31
            unsigned jp = (32u * n + j) & 1023u;
            unsigned ry = (169u * jp) & 1023u;
            unsigned cb = (32u * m + 239u * jp) & 1023u;
            unsigned fq = ((cb & ~3u) >> 2) * 3u + lane;        // quad in row
            if (fq >= ROW_F4) fq -= ROW_F4;
            v[it] = __ldcs(inb + ry * ROW_F4 + fq);
            slot[it] = (j << 5) + (lane ^ ((j + (j >> 3)) & 7u));
        }
        const bool extra = warp < 3u;                           // rows 32..34
        if (extra) {
            unsigned j  = warp + 32u;
            unsigned jp = (32u * n + j) & 1023u;
            unsigned ry = (169u * jp) & 1023u;
            unsigned cb = (32u * m + 239u * jp) & 1023u;
            unsigned fq = ((cb & ~3u) >> 2) * 3u + lane;
            if (fq >= ROW_F4) fq -= ROW_F4;
            v[4] = __ldcs(inb + ry * ROW_F4 + fq);
            slot[4] = (j << 5) + (lane ^ ((j + (j >> 3)) & 7u));
        }
        #pragma unroll
        for (unsigned it = 0; it < 4u; ++it) tile4[slot[it]] = v[it];
        if (extra) tile4[slot[4]] = v[4];
    }
    __syncthreads();

    // ---- Phase 2: write 32 output row-segments, 24 aligned float4 each ----
    if (lane < 24u) {
        const float* tf = reinterpret_cast<const float*>(tile4);
        const unsigned delta = (4u - (warp & 3u)) & 3u;         // (-k)&3, k≡warp mod 4

        // Per-(thread,e) invariants: output float L=4*lane+e -> tile row j=delta+u,
        // channel v; smem float f = C[e] + 3k.
        unsigned C[4], mm[4], base[4];
        #pragma unroll
        for (unsigned e = 0; e < 4u; ++e) {
            unsigned L  = 4u * lane + e;
            unsigned u  = L / 3u;
            unsigned vv = L - 3u * u;
            unsigned j  = delta + u;                            // <= 34
            unsigned s  = (0u - j) & 3u;                        // (3j)&3
            C[e]    = 3u * s + vv;
            mm[e]   = (j + (j >> 3)) & 7u;
            base[e] = j << 7;                                   // 128 floats per row
        }

        #pragma unroll
        for (unsigned it = 0; it < 4u; ++it) {
            unsigned k   = warp + 8u * it;
            unsigned t3k = 3u * k;
            float r[4];
            #pragma unroll
            for (unsigned e = 0; e < 4u; ++e) {
                unsigned f   = C[e] + t3k;
                unsigned pos = base[e] + (((f >> 2) ^ mm[e]) << 2) + (f & 3u);
                r[e] = tf[pos];
            }
            unsigned kp = 32u * m + k;
            unsigned a  = (169u * kp) & 1023u;
            unsigned ob = (32u * n - 239u * kp) & 1023u;
            unsigned sp = (ob + delta) & 1023u;                 // aligned start pixel
            unsigned wi = (sp >> 2) * 3u + lane;                // quad in out row
            if (wi >= ROW_F4) wi -= ROW_F4;
            float4 w;
            w.x = r[0]; w.y = r[1]; w.z = r[2]; w.w = r[3];
            __stcs(outb + a * ROW_F4 + wi, w);
        }
    }
}

extern "C" void kernel_launch(void* const* d_in, const int* in_sizes, int n_in,
                              void* d_out, int out_size) {
    (void)in_sizes; (void)n_in; (void)out_size;
    arnold_vec_kernel<<<BLOCKS, THREADS>>>((const float4*)d_in[0], (float4*)d_out);
}

// round 5
// speedup vs baseline: 1.0887x; 1.0887x over previous
#include <cuda_runtime.h>

// ArnoldCat ^7, n=1024: out[a,b] <- in[(239a+169b)&1023, (338a+239b)&1023].
//
// Lattice basis (round 3): (a,b) = (169k', j'-239k'), source = (169j', k'+239j').
// Tile (m,n): k'=32m+k, j'=32n+j.
//   Phase 1 (scalar gather): row j -> source row 169j', 96 consecutive floats from
//     3*cb_j, cb_j=(32m+239j')&1023. Element f=3k+c of that segment belongs to
//     output row k, channel c.
//   Output-ordered SMEM: osm[k*100 + 3*(j - delta_k) + c], delta_k=(-k)&3, stored
//     only when delta_k <= j < delta_k+32. Rows j=0..34 loaded (3-row overlap with
//     the n+1 tile; absorbed by L2).
//   Phase 2 (vector scatter): output row a=169k'&1023, window start pixel
//     sp=(ob+delta_k)&1023 with ob=(32n-239k')&1023; sp==0 mod 4 (ob≡k mod 4).
//     Window floats are CONTIGUOUS in osm -> 24 LDS.128 + 24 STG.128 per row.

static constexpr unsigned THREADS = 256u;
static constexpr unsigned BLOCKS  = 16u * 32u * 32u;   // batch x m x n
static constexpr unsigned IMG_F   = 1024u * 3072u;
static constexpr unsigned IMG_F4  = 1024u * 768u;

__global__ void __launch_bounds__(THREADS)
arnold_v5_kernel(const float* __restrict__ in, float4* __restrict__ out4) {
    __shared__ float osm[3200];                        // 32 rows x 100 floats

    const unsigned id    = blockIdx.x;
    const unsigned n     = id & 31u;
    const unsigned m     = (id >> 5) & 31u;
    const unsigned batch = id >> 10;
    const unsigned lane  = threadIdx.x & 31u;
    const unsigned warp  = threadIdx.x >> 5;

    const float* inb = in + batch * IMG_F;

    // ---- per-(lane,t) invariants for the SMEM scatter ----
    int      sbase[3];
    unsigned dlo[3];
    #pragma unroll
    for (unsigned t = 0; t < 3u; ++t) {
        unsigned f = lane + 32u * t;                   // float within 96-float segment
        unsigned k = f / 3u;                           // output row this float feeds
        unsigned c = f - 3u * k;                       // channel
        unsigned d = (4u - (k & 3u)) & 3u;             // delta_k = (-k)&3
        dlo[t]   = d;
        sbase[t] = (int)(k * 100u + c) - 3 * (int)d;   // + 3j at store time
    }

    // ---- Phase 1: load up to 5 source row segments (batched for MLP) ----
    float v[5][3];
    #pragma unroll
    for (unsigned r = 0; r < 5u; ++r) {
        const bool valid = (r < 4u) || (warp < 3u);
        unsigned j  = (r < 4u) ? (warp + 8u * r) : (32u + warp);
        unsigned jp = 32u * n + j;
        unsigned ry = (169u * jp) & 1023u;
        unsigned cb3 = ((32u * m + 239u * jp) & 1023u) * 3u;
        const float* rowp = inb + ry * 3072u;
        #pragma unroll
        for (unsigned t = 0; t < 3u; ++t) {
            unsigned o = cb3 + lane + 32u * t;
            if (o >= 3072u) o -= 3072u;                // rare row wrap
            if (valid) v[r][t] = __ldcs(rowp + o);     // stream: zero reuse
        }
    }
    // ---- scatter into output-ordered SMEM (addr = sbase + 3j, 1 IADD) ----
    #pragma unroll
    for (unsigned r = 0; r < 5u; ++r) {
        const bool valid = (r < 4u) || (warp < 3u);
        unsigned j = (r < 4u) ? (warp + 8u * r) : (32u + warp);
        #pragma unroll
        for (unsigned t = 0; t < 3u; ++t) {
            if (valid && (j - dlo[t] < 32u))           // unsigned: also rejects j<delta
                osm[sbase[t] + 3 * (int)j] = v[r][t];
        }
    }
    __syncthreads();

    // ---- Phase 2: 32 output rows, contiguous 24xfloat4 window per row ----
    if (lane < 24u) {
        const float4* osm4 = reinterpret_cast<const float4*>(osm);
        float4* outb = out4 + batch * IMG_F4;
        const unsigned d = (4u - (warp & 3u)) & 3u;    // delta_k, constant per warp
        #pragma unroll
        for (unsigned it = 0; it < 4u; ++it) {
            unsigned k  = warp + 8u * it;
            unsigned kp = 32u * m + k;
            unsigned a  = (169u * kp) & 1023u;                 // output row
            unsigned ob = (32u * n - 239u * kp) & 1023u;       // pixel for j=0
            unsigned sp = (ob + d) & 1023u;                    // aligned window start
            unsigned wi = (sp >> 2) * 3u + lane;               // quad in out row
            if (wi >= 768u) wi -= 768u;                        // row wrap
            float4 w = osm4[k * 25u + lane];                   // LDS.128, contiguous
            __stcs(outb + a * 768u + wi, w);                   // STG.128, coalesced
        }
    }
}

extern "C" void kernel_launch(void* const* d_in, const int* in_sizes, int n_in,
                              void* d_out, int out_size) {
    (void)in_sizes; (void)n_in; (void)out_size;
    arnold_v5_kernel<<<BLOCKS, THREADS>>>((const float*)d_in[0], (float4*)d_out);
}